// round 15
// baseline (speedup 1.0000x reference)
#include <cuda_runtime.h>
#include <cuda_fp16.h>
#include <cstdint>

// Problem constants
namespace {
constexpr int Bb = 8, Ss = 4096, Dh = 1024;
constexpr int M  = Bb * Ss;   // 32768
constexpr int K  = 1024;
// GEMM tiling (fp16 mma.m16n8k16 + ldmatrix), BK=32 halves = 64B rows
constexpr int BN = 64, BKH = 32;
constexpr int NT = K / BKH;                   // 32 chunks
constexpr int STAGES = 4;
constexpr int TILEB = BN * BKH * 2;           // 4096 B
// Scan chunking
constexpr int NC = 64;
constexpr int CL = Ss / NC;                   // 64
constexpr int NSEQ = Bb * Dh;                 // 8192
}

// Scratch
__device__ __half2 g_abh[(size_t)M * Dh];      // packed (a_t, b_t), 134 MB
__device__ __half  g_xh [(size_t)M * K];       // fp16 x
__device__ __half  g_hh [(size_t)M * Dh];      // fp16 scanned h
__device__ __half  g_wzh[(size_t)Dh * K];
__device__ __half  g_whh[(size_t)Dh * K];
__device__ __half  g_woh[(size_t)Dh * K];
__device__ float2  g_comp [(size_t)NC * NSEQ];
__device__ float   g_carry[(size_t)NC * NSEQ];

__device__ __forceinline__ float sigm(float x) { return 1.f / (1.f + __expf(-x)); }

__device__ __forceinline__ void cp16s(uint32_t saddr, const void* gsrc) {
    asm volatile("cp.async.cg.shared.global [%0], [%1], 16;" :: "r"(saddr), "l"(gsrc));
}

__device__ __forceinline__ void ldmx4(uint32_t* r, uint32_t a) {
    asm volatile("ldmatrix.sync.aligned.m8n8.x4.shared.b16 {%0,%1,%2,%3}, [%4];"
        : "=r"(r[0]), "=r"(r[1]), "=r"(r[2]), "=r"(r[3]) : "r"(a));
}

__device__ __forceinline__ void mma16(float* c, const uint32_t* a, const uint32_t* b) {
    asm volatile(
        "mma.sync.aligned.m16n8k16.row.col.f32.f16.f16.f32 "
        "{%0,%1,%2,%3}, {%4,%5,%6,%7}, {%8,%9}, {%0,%1,%2,%3};"
        : "+f"(c[0]), "+f"(c[1]), "+f"(c[2]), "+f"(c[3])
        : "r"(a[0]), "r"(a[1]), "r"(a[2]), "r"(a[3]), "r"(b[0]), "r"(b[1]));
}

// Swizzled 64B-row smem offset: 4 chunks of 16B per row, chunk ^= (row>>1)&3.
__device__ __forceinline__ uint32_t swz(int row, int ch) {
    return (uint32_t)row * 64u + (uint32_t)((ch ^ ((row >> 1) & 3)) << 4);
}

// fp32 -> fp16 conversion pass (16B loads, 8B stores, coalesced).
__global__ void __launch_bounds__(256) cvt_kernel(const float4* __restrict__ in,
                                                  __half2* __restrict__ out, int n4)
{
    int i = blockIdx.x * blockDim.x + threadIdx.x;
    if (i >= n4) return;
    float4 v = in[i];
    out[2 * i]     = __floats2half2_rn(v.x, v.y);
    out[2 * i + 1] = __floats2half2_rn(v.z, v.w);
}

// Load a ROWSx32-half tile (64B rows, swizzled). ROWS*4/256 cp.async per thread.
template <int ROWS>
__device__ __forceinline__ void load_tile(uint32_t sbase, const __half* g, int tid) {
#pragma unroll
    for (int i = 0; i < ROWS * 4 / 256; ++i) {
        int s = tid + i * 256;
        int row = s >> 2, ch = s & 3;
        cp16s(sbase + swz(row, ch), g + (size_t)row * K + ch * 8);
    }
}

// fp16 tensor-core GEMM, BK=32, 4-stage single-sync cp.async pipeline.
// DUAL : BMT=128. A=g_xh, W1=g_wzh, W2=g_whh -> gate epilogue -> g_abh,
//        plus fused per-chunk composite reduction -> g_comp (replaces scan_p1).
// !DUAL: BMT=256. A=g_hh, W1=g_woh -> + bias -> outF.
template <bool DUAL, int BMT>
__global__ void __launch_bounds__(256)
gemm_h(const float* __restrict__ b1, const float* __restrict__ b2,
       float* __restrict__ outF)
{
    extern __shared__ __align__(1024) char smem[];
    const uint32_t sb = (uint32_t)__cvta_generic_to_shared(smem);

    const int tid  = threadIdx.x;
    const int lane = tid & 31;
    const int warp = tid >> 5;
    const int wm   = warp & 3;     // 4 warps along M
    const int wn   = warp >> 2;    // 2 warps along N (32 cols each)
    const int gr   = lane >> 2;
    const int gc   = lane & 3;

    constexpr int WM  = BMT / 4;                 // rows per warp
    constexpr int NI  = WM / 16;                 // m16 blocks per warp
    constexpr int TILEA = BMT * BKH * 2;
    constexpr int NB  = DUAL ? 3 : 2;
    constexpr int STB = TILEA + (NB - 1) * TILEB;

    const int n0 = blockIdx.x * BN;   // x = N tile -> A reuse in L2 across CTAs
    const int m0 = blockIdx.y * BMT;

    const __half* A  = DUAL ? (const __half*)g_xh  : (const __half*)g_hh;
    const __half* W1 = DUAL ? (const __half*)g_wzh : (const __half*)g_woh;

    float accZ[NI][4][4];
    float accH[DUAL ? NI : 1][4][4];
#pragma unroll
    for (int i = 0; i < NI; ++i)
#pragma unroll
        for (int j = 0; j < 4; ++j)
#pragma unroll
            for (int r = 0; r < 4; ++r) { accZ[i][j][r] = 0.f; if (DUAL) accH[i][j][r] = 0.f; }

    // Per-lane ldmatrix address components.
    int arow[NI], aswz[NI];
#pragma unroll
    for (int i = 0; i < NI; ++i) {
        int row = wm * WM + i * 16 + (lane & 15);
        arow[i] = row * 64;
        aswz[i] = (row >> 1) & 3;
    }
    const int achi = lane >> 4;
    int brow[2], bswz[2];
#pragma unroll
    for (int p = 0; p < 2; ++p) {
        int n = wn * 32 + p * 16 + ((lane >> 4) << 3) + (lane & 7);
        brow[p] = n * 64;
        bswz[p] = (n >> 1) & 3;
    }
    const int bchi = (lane >> 3) & 1;

    auto load_chunk = [&](int j) {
        const int stage = j & (STAGES - 1);
        const int ko = j * BKH;
        const uint32_t base = sb + (uint32_t)stage * STB;
        load_tile<BMT>(base, A + (size_t)m0 * K + ko, tid);
        load_tile<BN>(base + TILEA, W1 + (size_t)n0 * K + ko, tid);
        if (DUAL)
            load_tile<BN>(base + TILEA + TILEB, (const __half*)g_whh + (size_t)n0 * K + ko, tid);
        asm volatile("cp.async.commit_group;");
    };

    // Prologue: fill STAGES-1 stages.
#pragma unroll
    for (int j = 0; j < STAGES - 1; ++j) load_chunk(j);

    for (int k = 0; k < NT; ++k) {
        // Tail-safe wait: with no commits after chunk NT-1, tighten the bound
        // so the last two chunks are actually guaranteed resident.
        if (k < NT - 2)       asm volatile("cp.async.wait_group 2;");
        else if (k == NT - 2) asm volatile("cp.async.wait_group 1;");
        else                  asm volatile("cp.async.wait_group 0;");
        __syncthreads();
        // Load chunk k+3 into buffer (k-1)&3 — freed by the barrier above.
        const int jn = k + STAGES - 1;
        if (jn < NT) load_chunk(jn);

        const int st = k & (STAGES - 1);
        const uint32_t abase  = sb + (uint32_t)st * STB;
        const uint32_t bbase1 = abase + TILEA;
        const uint32_t bbase2 = bbase1 + TILEB;

#pragma unroll
        for (int ks = 0; ks < 2; ++ks) {
            uint32_t afr[NI][4];
#pragma unroll
            for (int i = 0; i < NI; ++i) {
                const int ch = 2 * ks + achi;
                ldmx4(afr[i], abase + arow[i] + (uint32_t)(((ch ^ aswz[i])) << 4));
            }
#pragma unroll
            for (int p = 0; p < 2; ++p) {
                const int ch = 2 * ks + bchi;
                const uint32_t boff = brow[p] + (uint32_t)(((ch ^ bswz[p])) << 4);
                uint32_t bf1[4];
                ldmx4(bf1, bbase1 + boff);
#pragma unroll
                for (int i = 0; i < NI; ++i) {
                    mma16(accZ[i][2 * p + 0], afr[i], bf1 + 0);
                    mma16(accZ[i][2 * p + 1], afr[i], bf1 + 2);
                }
                if (DUAL) {
                    uint32_t bf2[4];
                    ldmx4(bf2, bbase2 + boff);
#pragma unroll
                    for (int i = 0; i < NI; ++i) {
                        mma16(accH[i][2 * p + 0], afr[i], bf2 + 0);
                        mma16(accH[i][2 * p + 1], afr[i], bf2 + 2);
                    }
                }
            }
        }
    }

    if (DUAL) __syncthreads();   // pipeline smem now free for the ab stage buffer

    // ab stage buffer for fused composite reduction: [128 rows][64 cols] uint32,
    // row stride 65 words to spread banks. 33280 B < 64 KB dynamic smem.
    uint32_t* ab_sm = reinterpret_cast<uint32_t*>(smem);

    // Epilogue
#pragma unroll
    for (int i = 0; i < NI; ++i)
#pragma unroll
        for (int j = 0; j < 4; ++j)
#pragma unroll
            for (int p = 0; p < 2; ++p) {
                const int rl  = wm * WM + i * 16 + gr + p * 8;   // row in tile
                const int row = m0 + rl;
                const int cl  = wn * 32 + j * 8 + gc * 2;        // col in tile
                const int col = n0 + cl;
                if (DUAL) {
                    float kz0 = accZ[i][j][2 * p + 0] + __ldg(&b1[col]);
                    float kz1 = accZ[i][j][2 * p + 1] + __ldg(&b1[col + 1]);
                    float kh0 = accH[i][j][2 * p + 0] + __ldg(&b2[col]);
                    float kh1 = accH[i][j][2 * p + 1] + __ldg(&b2[col + 1]);
                    // g(x) = x>=0 ? x+0.5 : sigmoid(x)   (== exp(log_g))
                    float g0 = (kh0 >= 0.f) ? (kh0 + 0.5f) : sigm(kh0);
                    float g1 = (kh1 >= 0.f) ? (kh1 + 0.5f) : sigm(kh1);
                    __half2 v0 = __floats2half2_rn(sigm(-kz0), sigm(kz0) * g0);
                    __half2 v1 = __floats2half2_rn(sigm(-kz1), sigm(kz1) * g1);
                    uint2 u;
                    u.x = *reinterpret_cast<uint32_t*>(&v0);
                    u.y = *reinterpret_cast<uint32_t*>(&v1);
                    *reinterpret_cast<uint2*>(&g_abh[(size_t)row * Dh + col]) = u;
                    ab_sm[rl * 65 + cl]     = u.x;   // same rounded values as global
                    ab_sm[rl * 65 + cl + 1] = u.y;
                } else {
                    float2 o;
                    o.x = accZ[i][j][2 * p + 0] + __ldg(&b1[col]);
                    o.y = accZ[i][j][2 * p + 1] + __ldg(&b1[col + 1]);
                    *reinterpret_cast<float2*>(&outF[(size_t)row * Dh + col]) = o;
                }
            }

    if (DUAL) {
        // Fused scan_p1: tile = 2 chunks of CL=64 rows x 64 cols, one batch.
        __syncthreads();
        if (tid < 2 * BN) {
            const int chunk = tid >> 6;          // 0..1
            const int cl    = tid & 63;
            float Av = 1.f, Bv = 0.f;
#pragma unroll 8
            for (int s = 0; s < CL; ++s) {
                uint32_t u = ab_sm[(chunk * CL + s) * 65 + cl];
                float2 v = __half22float2(*reinterpret_cast<__half2*>(&u));
                Av *= v.x;
                Bv  = fmaf(v.x, Bv, v.y);
            }
            const int b  = m0 >> 12;                         // batch
            const int c  = ((m0 & 4095) >> 6) + chunk;       // global s-chunk
            g_comp[(size_t)c * NSEQ + b * 1024 + n0 + cl] = make_float2(Av, Bv);
        }
    }
}

// ---- Chunked parallel scan: h_t = a_t * h_{t-1} + b_t (fp32 math, fp16 ab) ----
// (p1 is fused into the dual GEMM epilogue.)

__global__ void __launch_bounds__(256) scan_p2()
{
    const int bh = blockIdx.x * blockDim.x + threadIdx.x;
    float h = 0.f;
#pragma unroll
    for (int c = 0; c < NC; ++c) {
        const size_t idx = (size_t)c * NSEQ + bh;
        float2 cmp = g_comp[idx];
        g_carry[idx] = h;
        h = fmaf(cmp.x, h, cmp.y);
    }
}

// p3: 2 h-lanes per thread -> uint2 loads, coalesced 4B half2 stores.
__global__ void __launch_bounds__(256) scan_p3()
{
    const int t     = blockIdx.x * blockDim.x + threadIdx.x;  // 0..NC*NSEQ/2-1
    const int g2    = t & (NSEQ / 2 - 1);                     // 0..4095
    const int chunk = t >> 12;
    const int b   = g2 >> 9;
    const int h0  = (g2 & 511) * 2;
    const size_t base = ((size_t)b * Ss + (size_t)chunk * CL) * Dh + h0;
    float2 hc = *reinterpret_cast<const float2*>(
        &g_carry[(size_t)chunk * NSEQ + b * 1024 + h0]);
    float ha = hc.x, hb = hc.y;
#pragma unroll 8
    for (int s = 0; s < CL; ++s) {
        const size_t idx = base + (size_t)s * Dh;
        uint2 raw = *reinterpret_cast<const uint2*>(&g_abh[idx]);
        float2 v0 = __half22float2(*reinterpret_cast<__half2*>(&raw.x));
        float2 v1 = __half22float2(*reinterpret_cast<__half2*>(&raw.y));
        ha = fmaf(v0.x, ha, v0.y);
        hb = fmaf(v1.x, hb, v1.y);
        *reinterpret_cast<__half2*>(&g_hh[idx]) = __floats2half2_rn(ha, hb);
    }
}

extern "C" void kernel_launch(void* const* d_in, const int* in_sizes, int n_in,
                              void* d_out, int out_size)
{
    const float* x  = (const float*)d_in[0];
    const float* Wz = (const float*)d_in[1];
    const float* bz = (const float*)d_in[2];
    const float* Wh = (const float*)d_in[3];
    const float* bh = (const float*)d_in[4];
    const float* Wo = (const float*)d_in[5];
    const float* bo = (const float*)d_in[6];
    float* out = (float*)d_out;

    constexpr int BM_DUAL = 128, BM_OUT = 256;
    const int smem_dual = STAGES * (BM_DUAL * BKH * 2 + 2 * TILEB);  // 65536 B
    const int smem_out  = STAGES * (BM_OUT  * BKH * 2 + 1 * TILEB);  // 81920 B
    cudaFuncSetAttribute(gemm_h<true,  BM_DUAL>, cudaFuncAttributeMaxDynamicSharedMemorySize, smem_dual);
    cudaFuncSetAttribute(gemm_h<false, BM_OUT>,  cudaFuncAttributeMaxDynamicSharedMemorySize, smem_out);

    // 0) convert operands to fp16
    {
        __half2* xh;  cudaGetSymbolAddress((void**)&xh,  g_xh);
        __half2* wzh; cudaGetSymbolAddress((void**)&wzh, g_wzh);
        __half2* whh; cudaGetSymbolAddress((void**)&whh, g_whh);
        __half2* woh; cudaGetSymbolAddress((void**)&woh, g_woh);
        const int nx4 = (M * K) / 4;
        const int nw4 = (Dh * K) / 4;
        cvt_kernel<<<(nx4 + 255) / 256, 256>>>((const float4*)x,  xh,  nx4);
        cvt_kernel<<<(nw4 + 255) / 256, 256>>>((const float4*)Wz, wzh, nw4);
        cvt_kernel<<<(nw4 + 255) / 256, 256>>>((const float4*)Wh, whh, nw4);
        cvt_kernel<<<(nw4 + 255) / 256, 256>>>((const float4*)Wo, woh, nw4);
    }

    // 1) fused dual fp16 GEMM + gates -> g_abh, + fused chunk composites -> g_comp
    {
        dim3 grid(Dh / BN, M / BM_DUAL);   // (16, 256)
        gemm_h<true, BM_DUAL><<<grid, 256, smem_dual>>>(bz, bh, nullptr);
    }

    // 2) chunked parallel scan (fp32 math)
    scan_p2<<<NSEQ / 256, 256>>>();
    scan_p3<<<(NC * NSEQ / 2) / 256, 256>>>();

    // 3) output projection with bias
    {
        dim3 grid(Dh / BN, M / BM_OUT);    // (16, 128)
        gemm_h<false, BM_OUT><<<grid, 256, smem_out>>>(bo, nullptr, out);
    }
}

// round 17
// speedup vs baseline: 1.5069x; 1.5069x over previous
#include <cuda_runtime.h>
#include <cuda_fp16.h>
#include <cstdint>

// Problem constants
namespace {
constexpr int Bb = 8, Ss = 4096, Dh = 1024;
constexpr int M  = Bb * Ss;   // 32768
constexpr int K  = 1024;
// GEMM tiling (fp16 mma.m16n8k16 + ldmatrix), BK=32 halves = 64B rows
constexpr int BM = 128, BN = 64, BKH = 32;
constexpr int NT = K / BKH;                   // 32 chunks
constexpr int STAGES = 4;
constexpr int TILEA = BM * BKH * 2;           // 8192 B
constexpr int TILEB = BN * BKH * 2;           // 4096 B
// Scan chunking
constexpr int NC = 64;
constexpr int CL = Ss / NC;                   // 64
constexpr int NSEQ = Bb * Dh;                 // 8192
}

// Scratch
__device__ __half2 g_abh[(size_t)M * Dh];      // packed (a_t, b_t), 134 MB
__device__ __half  g_xh [(size_t)M * K];       // fp16 x
__device__ __half  g_hh [(size_t)M * Dh];      // fp16 scanned h
__device__ __half  g_wzh[(size_t)Dh * K];
__device__ __half  g_whh[(size_t)Dh * K];
__device__ __half  g_woh[(size_t)Dh * K];
__device__ float2  g_comp [(size_t)NC * NSEQ];
__device__ float   g_carry[(size_t)NC * NSEQ];

__device__ __forceinline__ float sigm(float x) { return 1.f / (1.f + __expf(-x)); }

__device__ __forceinline__ void cp16s(uint32_t saddr, const void* gsrc) {
    asm volatile("cp.async.cg.shared.global [%0], [%1], 16;" :: "r"(saddr), "l"(gsrc));
}

__device__ __forceinline__ void ldmx4(uint32_t* r, uint32_t a) {
    asm volatile("ldmatrix.sync.aligned.m8n8.x4.shared.b16 {%0,%1,%2,%3}, [%4];"
        : "=r"(r[0]), "=r"(r[1]), "=r"(r[2]), "=r"(r[3]) : "r"(a));
}

__device__ __forceinline__ void mma16(float* c, const uint32_t* a, const uint32_t* b) {
    asm volatile(
        "mma.sync.aligned.m16n8k16.row.col.f32.f16.f16.f32 "
        "{%0,%1,%2,%3}, {%4,%5,%6,%7}, {%8,%9}, {%0,%1,%2,%3};"
        : "+f"(c[0]), "+f"(c[1]), "+f"(c[2]), "+f"(c[3])
        : "r"(a[0]), "r"(a[1]), "r"(a[2]), "r"(a[3]), "r"(b[0]), "r"(b[1]));
}

// Swizzled 64B-row smem offset: 4 chunks of 16B per row, chunk ^= (row>>1)&3.
__device__ __forceinline__ uint32_t swz(int row, int ch) {
    return (uint32_t)row * 64u + (uint32_t)((ch ^ ((row >> 1) & 3)) << 4);
}

// fp32 -> fp16 conversion pass (16B loads, 8B stores, coalesced).
__global__ void __launch_bounds__(256) cvt_kernel(const float4* __restrict__ in,
                                                  __half2* __restrict__ out, int n4)
{
    int i = blockIdx.x * blockDim.x + threadIdx.x;
    if (i >= n4) return;
    float4 v = in[i];
    out[2 * i]     = __floats2half2_rn(v.x, v.y);
    out[2 * i + 1] = __floats2half2_rn(v.z, v.w);
}

// Load one 128x32-half A tile (64B rows, swizzled). 2 cp.async/thread @256thr.
__device__ __forceinline__ void load_tileA(uint32_t sbase, const __half* g, int tid) {
#pragma unroll
    for (int i = 0; i < 2; ++i) {
        int s = tid + i * 256;          // 0..511
        int row = s >> 2, ch = s & 3;
        cp16s(sbase + swz(row, ch), g + (size_t)row * K + ch * 8);
    }
}
// Load one 64x32-half B tile. 1 cp.async/thread.
__device__ __forceinline__ void load_tileB(uint32_t sbase, const __half* g, int tid) {
    int row = tid >> 2, ch = tid & 3;
    cp16s(sbase + swz(row, ch), g + (size_t)row * K + ch * 8);
}

// fp16 tensor-core GEMM, BK=32, 4-stage single-sync cp.async pipeline.
// DUAL : A=g_xh, W1=g_wzh, W2=g_whh -> gate epilogue -> g_abh (fp16 pairs)
// !DUAL: A=g_hh, W1=g_woh           -> + bias        -> outF
template <bool DUAL>
__global__ void __launch_bounds__(256)
gemm_h(const float* __restrict__ b1, const float* __restrict__ b2,
       float* __restrict__ outF)
{
    extern __shared__ __align__(1024) char smem[];
    const uint32_t sb = (uint32_t)__cvta_generic_to_shared(smem);

    const int tid  = threadIdx.x;
    const int lane = tid & 31;
    const int warp = tid >> 5;
    const int wm   = warp & 3;     // 4 warps along M (32 rows)
    const int wn   = warp >> 2;    // 2 warps along N (32 cols)
    const int gr   = lane >> 2;
    const int gc   = lane & 3;

    const int n0 = blockIdx.x * BN;   // x = N tile -> A reuse in L2 across CTAs
    const int m0 = blockIdx.y * BM;

    const __half* A  = DUAL ? (const __half*)g_xh  : (const __half*)g_hh;
    const __half* W1 = DUAL ? (const __half*)g_wzh : (const __half*)g_woh;

    constexpr int NB  = DUAL ? 3 : 2;               // tiles per stage
    constexpr int STB = TILEA + (NB - 1) * TILEB;   // stage bytes

    float accZ[2][4][4];
    float accH[DUAL ? 2 : 1][4][4];
#pragma unroll
    for (int i = 0; i < 2; ++i)
#pragma unroll
        for (int j = 0; j < 4; ++j)
#pragma unroll
            for (int r = 0; r < 4; ++r) { accZ[i][j][r] = 0.f; if (DUAL) accH[i][j][r] = 0.f; }

    // Per-lane ldmatrix address components.
    int arow[2], aswz[2];
#pragma unroll
    for (int i = 0; i < 2; ++i) {
        arow[i] = (wm * 32 + i * 16 + (lane & 15)) * 64;
        aswz[i] = ((wm * 32 + i * 16 + (lane & 15)) >> 1) & 3;
    }
    const int achi = lane >> 4;
    int brow[2], bswz[2];
#pragma unroll
    for (int p = 0; p < 2; ++p) {
        int n = wn * 32 + p * 16 + ((lane >> 4) << 3) + (lane & 7);
        brow[p] = n * 64;
        bswz[p] = (n >> 1) & 3;
    }
    const int bchi = (lane >> 3) & 1;

    auto load_chunk = [&](int j) {
        const int stage = j & (STAGES - 1);
        const int ko = j * BKH;
        const uint32_t base = sb + (uint32_t)stage * STB;
        load_tileA(base, A + (size_t)m0 * K + ko, tid);
        load_tileB(base + TILEA, W1 + (size_t)n0 * K + ko, tid);
        if (DUAL)
            load_tileB(base + TILEA + TILEB, (const __half*)g_whh + (size_t)n0 * K + ko, tid);
        asm volatile("cp.async.commit_group;");
    };

    // Prologue: fill STAGES-1 stages.
#pragma unroll
    for (int j = 0; j < STAGES - 1; ++j) load_chunk(j);

    for (int k = 0; k < NT; ++k) {
        // Tail-safe wait: no commits happen after chunk NT-1 is issued, so the
        // allowed-outstanding count must shrink near the end or the last two
        // chunks would not be guaranteed resident.
        if (k < NT - 2)       asm volatile("cp.async.wait_group 2;");
        else if (k == NT - 2) asm volatile("cp.async.wait_group 1;");
        else                  asm volatile("cp.async.wait_group 0;");
        __syncthreads();
        // Load chunk k+3 into buffer (k-1)&3 — freed by the barrier above,
        // so one sync per iteration suffices.
        const int jn = k + STAGES - 1;
        if (jn < NT) load_chunk(jn);

        const int st = k & (STAGES - 1);
        const uint32_t abase  = sb + (uint32_t)st * STB;
        const uint32_t bbase1 = abase + TILEA;
        const uint32_t bbase2 = bbase1 + TILEB;

#pragma unroll
        for (int ks = 0; ks < 2; ++ks) {
            uint32_t afr[2][4];
#pragma unroll
            for (int i = 0; i < 2; ++i) {
                const int ch = 2 * ks + achi;
                ldmx4(afr[i], abase + arow[i] + (uint32_t)(((ch ^ aswz[i])) << 4));
            }
#pragma unroll
            for (int p = 0; p < 2; ++p) {
                const int ch = 2 * ks + bchi;
                const uint32_t boff = brow[p] + (uint32_t)(((ch ^ bswz[p])) << 4);
                uint32_t bf1[4];
                ldmx4(bf1, bbase1 + boff);
#pragma unroll
                for (int i = 0; i < 2; ++i) {
                    mma16(accZ[i][2 * p + 0], afr[i], bf1 + 0);
                    mma16(accZ[i][2 * p + 1], afr[i], bf1 + 2);
                }
                if (DUAL) {
                    uint32_t bf2[4];
                    ldmx4(bf2, bbase2 + boff);
#pragma unroll
                    for (int i = 0; i < 2; ++i) {
                        mma16(accH[i][2 * p + 0], afr[i], bf2 + 0);
                        mma16(accH[i][2 * p + 1], afr[i], bf2 + 2);
                    }
                }
            }
        }
    }

    // Epilogue
#pragma unroll
    for (int i = 0; i < 2; ++i)
#pragma unroll
        for (int j = 0; j < 4; ++j)
#pragma unroll
            for (int p = 0; p < 2; ++p) {
                const int row = m0 + wm * 32 + i * 16 + gr + p * 8;
                const int col = n0 + wn * 32 + j * 8 + gc * 2;
                if (DUAL) {
                    float kz0 = accZ[i][j][2 * p + 0] + __ldg(&b1[col]);
                    float kz1 = accZ[i][j][2 * p + 1] + __ldg(&b1[col + 1]);
                    float kh0 = accH[i][j][2 * p + 0] + __ldg(&b2[col]);
                    float kh1 = accH[i][j][2 * p + 1] + __ldg(&b2[col + 1]);
                    // g(x) = x>=0 ? x+0.5 : sigmoid(x)   (== exp(log_g))
                    float g0 = (kh0 >= 0.f) ? (kh0 + 0.5f) : sigm(kh0);
                    float g1 = (kh1 >= 0.f) ? (kh1 + 0.5f) : sigm(kh1);
                    __half2 v0 = __floats2half2_rn(sigm(-kz0), sigm(kz0) * g0);
                    __half2 v1 = __floats2half2_rn(sigm(-kz1), sigm(kz1) * g1);
                    uint2 u;
                    u.x = *reinterpret_cast<uint32_t*>(&v0);
                    u.y = *reinterpret_cast<uint32_t*>(&v1);
                    *reinterpret_cast<uint2*>(&g_abh[(size_t)row * Dh + col]) = u;
                } else {
                    float2 o;
                    o.x = accZ[i][j][2 * p + 0] + __ldg(&b1[col]);
                    o.y = accZ[i][j][2 * p + 1] + __ldg(&b1[col + 1]);
                    *reinterpret_cast<float2*>(&outF[(size_t)row * Dh + col]) = o;
                }
            }
}

// ---- Chunked parallel scan: h_t = a_t * h_{t-1} + b_t (fp32 math, fp16 ab) ----
__global__ void __launch_bounds__(256) scan_p1()
{
    const int t     = blockIdx.x * blockDim.x + threadIdx.x;
    const int bh    = t & (NSEQ - 1);
    const int chunk = t >> 13;
    const int b  = bh >> 10;
    const int hh = bh & 1023;
    const size_t base = ((size_t)b * Ss + (size_t)chunk * CL) * Dh + hh;
    float A = 1.f, Bv = 0.f;
#pragma unroll 8
    for (int s = 0; s < CL; ++s) {
        float2 v = __half22float2(g_abh[base + (size_t)s * Dh]);
        A  *= v.x;
        Bv  = fmaf(v.x, Bv, v.y);
    }
    g_comp[(size_t)chunk * NSEQ + bh] = make_float2(A, Bv);
}

__global__ void __launch_bounds__(256) scan_p2()
{
    const int bh = blockIdx.x * blockDim.x + threadIdx.x;
    float h = 0.f;
#pragma unroll
    for (int c = 0; c < NC; ++c) {
        const size_t idx = (size_t)c * NSEQ + bh;
        float2 cmp = g_comp[idx];
        g_carry[idx] = h;
        h = fmaf(cmp.x, h, cmp.y);
    }
}

// p3: 2 h-lanes per thread -> uint2 loads of g_abh, coalesced 4B half2 stores.
__global__ void __launch_bounds__(256) scan_p3()
{
    const int t     = blockIdx.x * blockDim.x + threadIdx.x;  // 0..NC*NSEQ/2-1
    const int g2    = t & (NSEQ / 2 - 1);                     // 0..4095
    const int chunk = t >> 12;
    const int b   = g2 >> 9;
    const int h0  = (g2 & 511) * 2;
    const size_t base = ((size_t)b * Ss + (size_t)chunk * CL) * Dh + h0;
    float2 hc = *reinterpret_cast<const float2*>(
        &g_carry[(size_t)chunk * NSEQ + b * 1024 + h0]);
    float ha = hc.x, hb = hc.y;
#pragma unroll 8
    for (int s = 0; s < CL; ++s) {
        const size_t idx = base + (size_t)s * Dh;
        uint2 raw = *reinterpret_cast<const uint2*>(&g_abh[idx]);
        float2 v0 = __half22float2(*reinterpret_cast<__half2*>(&raw.x));
        float2 v1 = __half22float2(*reinterpret_cast<__half2*>(&raw.y));
        ha = fmaf(v0.x, ha, v0.y);
        hb = fmaf(v1.x, hb, v1.y);
        *reinterpret_cast<__half2*>(&g_hh[idx]) = __floats2half2_rn(ha, hb);
    }
}

extern "C" void kernel_launch(void* const* d_in, const int* in_sizes, int n_in,
                              void* d_out, int out_size)
{
    const float* x  = (const float*)d_in[0];
    const float* Wz = (const float*)d_in[1];
    const float* bz = (const float*)d_in[2];
    const float* Wh = (const float*)d_in[3];
    const float* bh = (const float*)d_in[4];
    const float* Wo = (const float*)d_in[5];
    const float* bo = (const float*)d_in[6];
    float* out = (float*)d_out;

    const int smem_dual   = STAGES * (TILEA + 2 * TILEB);  // 65536 B -> 3 CTAs/SM
    const int smem_single = STAGES * (TILEA + 1 * TILEB);  // 49152 B
    cudaFuncSetAttribute(gemm_h<true>,  cudaFuncAttributeMaxDynamicSharedMemorySize, smem_dual);
    cudaFuncSetAttribute(gemm_h<false>, cudaFuncAttributeMaxDynamicSharedMemorySize, smem_single);

    // 0) convert operands to fp16
    {
        __half2* xh;  cudaGetSymbolAddress((void**)&xh,  g_xh);
        __half2* wzh; cudaGetSymbolAddress((void**)&wzh, g_wzh);
        __half2* whh; cudaGetSymbolAddress((void**)&whh, g_whh);
        __half2* woh; cudaGetSymbolAddress((void**)&woh, g_woh);
        const int nx4 = (M * K) / 4;
        const int nw4 = (Dh * K) / 4;
        cvt_kernel<<<(nx4 + 255) / 256, 256>>>((const float4*)x,  xh,  nx4);
        cvt_kernel<<<(nw4 + 255) / 256, 256>>>((const float4*)Wz, wzh, nw4);
        cvt_kernel<<<(nw4 + 255) / 256, 256>>>((const float4*)Wh, whh, nw4);
        cvt_kernel<<<(nw4 + 255) / 256, 256>>>((const float4*)Wo, woh, nw4);
    }

    dim3 grid(Dh / BN, M / BM);   // (16, 256): x = N tile for A reuse in L2

    // 1) fused dual fp16 GEMM + gate nonlinearities -> packed fp16 (a, b)
    gemm_h<true><<<grid, 256, smem_dual>>>(bz, bh, nullptr);

    // 2) chunked parallel scan (fp32 math)
    scan_p1<<<(NC * NSEQ) / 256, 256>>>();
    scan_p2<<<NSEQ / 256, 256>>>();
    scan_p3<<<(NC * NSEQ / 2) / 256, 256>>>();

    // 3) output projection with bias
    gemm_h<false><<<grid, 256, smem_single>>>(bo, nullptr, out);
}